// round 11
// baseline (speedup 1.0000x reference)
#include <cuda_runtime.h>
#include <cuda_fp16.h>
#include <cstdint>

#define NV 40962
#define KR 19
#define NC 64            // C_in == C_out == 64
#define NBATCH 4
#define TILE_M 128
#define TILES_PER_B 321  // ceil(40962/128)
#define NTILES (NBATCH * TILES_PER_B)

// -------- device scratch (allocation-free rule: __device__ globals) --------
// x[b][v][64] fp16, 128B per vertex row
__device__ __align__(1024) __half g_xt[(size_t)NBATCH * NV * NC];   // ~21 MB
// per-chunk W tile: g_w[k][o][64] fp16 (row = 128B)
__device__ __align__(1024) __half g_w[KR * NC * NC];                // 152 KB

// ---------------------------- helpers ----------------------------------
__device__ __forceinline__ uint32_t smem_to_u32(const void* p) {
    uint32_t a;
    asm("{ .reg .u64 t; cvta.to.shared.u64 t, %1; cvt.u32.u64 %0, t; }"
        : "=r"(a) : "l"(p));
    return a;
}

#define SWZ(off) ((off) ^ (((off) >> 3) & 0x70))

__device__ __forceinline__ void cp16(uint32_t saddr, const void* gaddr) {
    asm volatile("cp.async.cg.shared.global [%0], [%1], 16;"
                 :: "r"(saddr), "l"(gaddr) : "memory");
}
__device__ __forceinline__ void cp_commit() {
    asm volatile("cp.async.commit_group;" ::: "memory");
}
__device__ __forceinline__ void cp_wait1() {
    asm volatile("cp.async.wait_group 1;" ::: "memory");
}

__device__ __forceinline__ void ldsm_x4(uint32_t& r0, uint32_t& r1, uint32_t& r2,
                                        uint32_t& r3, uint32_t a) {
    asm volatile("ldmatrix.sync.aligned.m8n8.x4.shared.b16 {%0,%1,%2,%3}, [%4];"
                 : "=r"(r0), "=r"(r1), "=r"(r2), "=r"(r3) : "r"(a));
}

__device__ __forceinline__ void mma_f16(float* c, uint32_t a0, uint32_t a1,
                                        uint32_t a2, uint32_t a3,
                                        uint32_t b0, uint32_t b1) {
    asm volatile(
        "mma.sync.aligned.m16n8k16.row.col.f32.f16.f16.f32 "
        "{%0,%1,%2,%3}, {%4,%5,%6,%7}, {%8,%9}, {%0,%1,%2,%3};"
        : "+f"(c[0]), "+f"(c[1]), "+f"(c[2]), "+f"(c[3])
        : "r"(a0), "r"(a1), "r"(a2), "r"(a3), "r"(b0), "r"(b1));
}

// ------------------------------ prep kernels --------------------------------
// W[o][19*64] -> g_w[k][o][c] fp16
__global__ void prep_w_kernel(const float* __restrict__ W) {
    int i = blockIdx.x * blockDim.x + threadIdx.x;
    if (i >= NC * KR * NC) return;
    int o = i / (KR * NC);
    int kk = i % (KR * NC);
    int k = kk >> 6, c = kk & 63;
    g_w[((size_t)k * NC + o) * NC + c] = __float2half(W[i]);
}

// Transpose x[b][c][v] -> xt[b][v][c] fp16
__global__ void prep_x_kernel(const float* __restrict__ x) {
    __shared__ float s[64][65];
    int b = blockIdx.y;
    int v0 = blockIdx.x * 64;
    int tid = threadIdx.x;  // 256
    for (int i = tid; i < 64 * 64; i += 256) {
        int c = i >> 6, vi = i & 63;
        int v = v0 + vi;
        s[c][vi] = (v < NV) ? x[((size_t)b * NC + c) * NV + v] : 0.f;
    }
    __syncthreads();
    for (int i = tid; i < 64 * 32; i += 256) {
        int vi = i >> 5, g = i & 31;
        int v = v0 + vi;
        if (v >= NV) continue;
        int c0 = g * 2;
        __half2 h2 = __floats2half2_rn(s[c0][vi], s[c0 + 1][vi]);
        *(__half2*)(g_xt + ((size_t)b * NV + v) * NC + c0) = h2;
    }
}

// ------------------------------ main kernel ---------------------------------
// smem layout (bytes):
#define OFF_BIAS  0          // 64 floats, pad to 512
#define OFF_IDX   512        // 128*19*2 (u16) = 4864 -> ends 5376
#define OFF_A     6144       // 2 stages x (128 rows x 128B) = 32768 (1024-aligned)
#define OFF_W     38912      // 2 stages x (64 rows x 128B)  = 16384
#define SMEM_TOTAL 55296
#define A_STAGE 16384
#define W_STAGE 8192

__global__ __launch_bounds__(256, 4) void conv_main(const int* __restrict__ neigh,
                                                    const float* __restrict__ bias,
                                                    float* __restrict__ out) {
    extern __shared__ char smem[];
    uint32_t sb = smem_to_u32(smem);
    const int tid = threadIdx.x;
    const int wid = tid >> 5, lid = tid & 31;
    const int b = blockIdx.x / TILES_PER_B;
    const int t = blockIdx.x % TILES_PER_B;
    const int vbase = t * TILE_M;
    int rows = NV - vbase; if (rows > TILE_M) rows = TILE_M;

    if (tid < NC) ((float*)(smem + OFF_BIAS))[tid] = bias[tid];

    // neighbor indices -> smem as u16 (NV < 65536)
    unsigned short* s_idx = (unsigned short*)(smem + OFF_IDX);
    {
        int tot = rows * KR;
        const int* src = neigh + (size_t)vbase * KR;
        for (int i = tid; i < tot; i += 256) s_idx[i] = (unsigned short)src[i];
    }
    __syncthreads();

    const __half* xt = g_xt + (size_t)b * NV * NC;

    // ---- gather one chunk into stage (k & 1) ----
    const int seg = tid & 7;          // 16B segment in a 128B row
    const int r0g = tid >> 3;         // 0..31
    auto issue_chunk = [&](int k) {
        int stage = k & 1;
        uint32_t abase = sb + OFF_A + stage * A_STAGE;
        #pragma unroll
        for (int j = 0; j < 4; j++) {
            int r = r0g + j * 32;
            int rr = (r < rows) ? r : 0;
            uint32_t v = s_idx[rr * KR + k];
            const char* g = (const char*)(xt + (size_t)v * NC) + seg * 16;
            cp16(abase + SWZ((uint32_t)(r * 128 + seg * 16)), g);
        }
        uint32_t wbase = sb + OFF_W + stage * W_STAGE;
        const char* wsrc = (const char*)(g_w + (size_t)k * NC * NC);
        #pragma unroll
        for (int j = 0; j < 2; j++) {
            int r = r0g + j * 32;   // 0..63
            uint32_t off = (uint32_t)(r * 128 + seg * 16);
            cp16(wbase + SWZ(off), wsrc + off);
        }
        cp_commit();
    };

    // ---- warp tiling: 4 M-warps x 2 N-warps; warp tile 32x32 ----
    const int wm = wid & 3;
    const int wn = wid >> 2;
    float acc[2][4][4];
    #pragma unroll
    for (int mt = 0; mt < 2; mt++)
        #pragma unroll
        for (int nt = 0; nt < 4; nt++)
            #pragma unroll
            for (int i = 0; i < 4; i++) acc[mt][nt][i] = 0.f;

    // ldmatrix lane address components (tile-relative byte offsets, pre-swizzle)
    const uint32_t aRow = (uint32_t)(wm * 32 + (lid & 7) + 8 * ((lid >> 3) & 1)) << 7;
    const uint32_t aColLane = (uint32_t)(lid >> 4) << 4;
    const uint32_t bRow = (uint32_t)(wn * 32 + (lid & 7) + 8 * (lid >> 4)) << 7;
    const uint32_t bColLane = (uint32_t)((lid >> 3) & 1) << 4;

    // 2-stage ring, issue-ahead-1, two barriers per chunk (proven schedule):
    //   issue(k+1) writes stage (k+1)&1 == (k-1)&1, fully consumed by MMA(k-1)
    //   before the trailing barrier of iter k-1.
    //   wait_group 1 leaves only group k+1 pending => group k complete; the
    //   leading barrier publishes all threads' stage-k data before ldmatrix.
    issue_chunk(0);

    for (int k = 0; k < KR; k++) {
        if (k + 1 < KR) issue_chunk(k + 1);
        else cp_commit();            // keep per-thread group counts uniform
        cp_wait1();
        __syncthreads();

        const int stage = k & 1;
        const uint32_t aT = sb + OFF_A + stage * A_STAGE;
        const uint32_t bT = sb + OFF_W + stage * W_STAGE;

        // Register-diet schedule: Bf[8] persists per ks; Af[4] per mt only.
        #pragma unroll
        for (int ks = 0; ks < 4; ks++) {
            const uint32_t kb = (uint32_t)(ks * 32);
            uint32_t Bf[8];
            #pragma unroll
            for (int p = 0; p < 2; p++) {
                uint32_t off = bRow + ((uint32_t)p << 11) + kb + bColLane;
                ldsm_x4(Bf[p * 4 + 0], Bf[p * 4 + 1], Bf[p * 4 + 2], Bf[p * 4 + 3],
                        bT + SWZ(off));
            }
            #pragma unroll
            for (int mt = 0; mt < 2; mt++) {
                uint32_t Af[4];
                uint32_t off = aRow + ((uint32_t)mt << 11) + kb + aColLane;
                ldsm_x4(Af[0], Af[1], Af[2], Af[3], aT + SWZ(off));
                #pragma unroll
                for (int nt = 0; nt < 4; nt++)
                    mma_f16(acc[mt][nt], Af[0], Af[1], Af[2], Af[3],
                            Bf[nt * 2], Bf[nt * 2 + 1]);
            }
        }
        __syncthreads();   // stage consumed by all warps before issue(k+2)
    }

    // ---- epilogue: stage via smem for coalesced [o][v] stores ----
    float* s_out = (float*)(smem + OFF_A);   // 32 KB = both A stages
    #pragma unroll
    for (int mt = 0; mt < 2; mt++) {
        int r = wm * 32 + mt * 16 + (lid >> 2);
        #pragma unroll
        for (int nt = 0; nt < 4; nt++) {
            int o = wn * 32 + nt * 8 + (lid & 3) * 2;
            s_out[(o + 0) * 128 + r]     = acc[mt][nt][0];
            s_out[(o + 1) * 128 + r]     = acc[mt][nt][1];
            s_out[(o + 0) * 128 + r + 8] = acc[mt][nt][2];
            s_out[(o + 1) * 128 + r + 8] = acc[mt][nt][3];
        }
    }
    __syncthreads();

    const float* bs = (const float*)(smem + OFF_BIAS);
    float* ob = out + (size_t)b * NC * NV + vbase;
    #pragma unroll
    for (int i = 0; i < 32; i++) {
        int idx = tid + i * 256;
        int o = idx >> 7, v = idx & 127;
        if (v < rows) ob[(size_t)o * NV + v] = s_out[idx] + bs[o];
    }
}

// ------------------------------ launch --------------------------------------
extern "C" void kernel_launch(void* const* d_in, const int* in_sizes, int n_in,
                              void* d_out, int out_size) {
    const float* x     = (const float*)d_in[0];
    const int*   neigh = (const int*)d_in[1];
    const float* W     = (const float*)d_in[2];
    const float* bias  = (const float*)d_in[3];
    float* out = (float*)d_out;

    cudaFuncSetAttribute(conv_main, cudaFuncAttributeMaxDynamicSharedMemorySize, SMEM_TOTAL);

    prep_w_kernel<<<(NC * KR * NC + 255) / 256, 256>>>(W);
    prep_x_kernel<<<dim3((NV + 63) / 64, NBATCH), 256>>>(x);
    conv_main<<<NTILES, 256, SMEM_TOTAL>>>(neigh, bias, out);
}

// round 12
// speedup vs baseline: 1.1468x; 1.1468x over previous
#include <cuda_runtime.h>
#include <cuda_fp16.h>
#include <cstdint>

#define NV 40962
#define KR 19
#define NC 64            // C_in == C_out == 64
#define NBATCH 4
#define TILE_M 128
#define TILES_PER_B 321  // ceil(40962/128)
#define NTILES (NBATCH * TILES_PER_B)

// -------- device scratch (allocation-free rule: __device__ globals) --------
// x[b][v][64] fp16, 128B per vertex row
__device__ __align__(1024) __half g_xt[(size_t)NBATCH * NV * NC];   // ~21 MB
// per-chunk W tile: g_w[k][o][64] fp16 (row = 128B)
__device__ __align__(1024) __half g_w[KR * NC * NC];                // 152 KB

// ---------------------------- helpers ----------------------------------
__device__ __forceinline__ uint32_t smem_to_u32(const void* p) {
    uint32_t a;
    asm("{ .reg .u64 t; cvta.to.shared.u64 t, %1; cvt.u32.u64 %0, t; }"
        : "=r"(a) : "l"(p));
    return a;
}

#define SWZ(off) ((off) ^ (((off) >> 3) & 0x70))

__device__ __forceinline__ void cp16(uint32_t saddr, const void* gaddr) {
    asm volatile("cp.async.cg.shared.global [%0], [%1], 16;"
                 :: "r"(saddr), "l"(gaddr) : "memory");
}
__device__ __forceinline__ void cp_commit() {
    asm volatile("cp.async.commit_group;" ::: "memory");
}
__device__ __forceinline__ void cp_wait3() {
    asm volatile("cp.async.wait_group 3;" ::: "memory");
}

__device__ __forceinline__ void ldsm_x4(uint32_t& r0, uint32_t& r1, uint32_t& r2,
                                        uint32_t& r3, uint32_t a) {
    asm volatile("ldmatrix.sync.aligned.m8n8.x4.shared.b16 {%0,%1,%2,%3}, [%4];"
                 : "=r"(r0), "=r"(r1), "=r"(r2), "=r"(r3) : "r"(a));
}

__device__ __forceinline__ void mma_f16(float* c, uint32_t a0, uint32_t a1,
                                        uint32_t a2, uint32_t a3,
                                        uint32_t b0, uint32_t b1) {
    asm volatile(
        "mma.sync.aligned.m16n8k16.row.col.f32.f16.f16.f32 "
        "{%0,%1,%2,%3}, {%4,%5,%6,%7}, {%8,%9}, {%0,%1,%2,%3};"
        : "+f"(c[0]), "+f"(c[1]), "+f"(c[2]), "+f"(c[3])
        : "r"(a0), "r"(a1), "r"(a2), "r"(a3), "r"(b0), "r"(b1));
}

// ------------------------------ prep kernels --------------------------------
// W[o][19*64] -> g_w[k][o][c] fp16
__global__ void prep_w_kernel(const float* __restrict__ W) {
    int i = blockIdx.x * blockDim.x + threadIdx.x;
    if (i >= NC * KR * NC) return;
    int o = i / (KR * NC);
    int kk = i % (KR * NC);
    int k = kk >> 6, c = kk & 63;
    g_w[((size_t)k * NC + o) * NC + c] = __float2half(W[i]);
}

// Transpose x[b][c][v] -> xt[b][v][c] fp16
__global__ void prep_x_kernel(const float* __restrict__ x) {
    __shared__ float s[64][65];
    int b = blockIdx.y;
    int v0 = blockIdx.x * 64;
    int tid = threadIdx.x;  // 256
    for (int i = tid; i < 64 * 64; i += 256) {
        int c = i >> 6, vi = i & 63;
        int v = v0 + vi;
        s[c][vi] = (v < NV) ? x[((size_t)b * NC + c) * NV + v] : 0.f;
    }
    __syncthreads();
    for (int i = tid; i < 64 * 32; i += 256) {
        int vi = i >> 5, g = i & 31;
        int v = v0 + vi;
        if (v >= NV) continue;
        int c0 = g * 2;
        __half2 h2 = __floats2half2_rn(s[c0][vi], s[c0 + 1][vi]);
        *(__half2*)(g_xt + ((size_t)b * NV + v) * NC + c0) = h2;
    }
}

// ------------------------------ main kernel ---------------------------------
// smem layout (bytes):
#define OFF_BIAS  0          // 64 floats, pad to 512
#define OFF_IDX   512        // 128*19*2 (u16) = 4864 -> ends 5376
#define OFF_A     6144       // 3 stages x (128 rows x 128B) = 49152
#define OFF_W     55296      // 2 stages x (64 rows x 128B)  = 16384
#define SMEM_TOTAL 71680
#define A_STAGE 16384
#define W_STAGE 8192

__global__ __launch_bounds__(256, 3) void conv_main(const int* __restrict__ neigh,
                                                    const float* __restrict__ bias,
                                                    float* __restrict__ out) {
    extern __shared__ char smem[];
    uint32_t sb = smem_to_u32(smem);
    const int tid = threadIdx.x;
    const int wid = tid >> 5, lid = tid & 31;
    const int b = blockIdx.x / TILES_PER_B;
    const int t = blockIdx.x % TILES_PER_B;
    const int vbase = t * TILE_M;
    int rows = NV - vbase; if (rows > TILE_M) rows = TILE_M;

    if (tid < NC) ((float*)(smem + OFF_BIAS))[tid] = bias[tid];

    // neighbor indices -> smem as u16 (NV < 65536)
    unsigned short* s_idx = (unsigned short*)(smem + OFF_IDX);
    {
        int tot = rows * KR;
        const int* src = neigh + (size_t)vbase * KR;
        for (int i = tid; i < tot; i += 256) s_idx[i] = (unsigned short)src[i];
    }
    __syncthreads();

    const __half* xt = g_xt + (size_t)b * NV * NC;

    const int seg = tid & 7;          // 16B segment in a 128B row
    const int r0g = tid >> 3;         // 0..31

    // A gather for chunk k -> A stage (k % 3); one commit group.
    auto issue_A = [&](int k, int astage) {
        uint32_t abase = sb + OFF_A + astage * A_STAGE;
        #pragma unroll
        for (int j = 0; j < 4; j++) {
            int r = r0g + j * 32;
            int rr = (r < rows) ? r : 0;
            uint32_t v = s_idx[rr * KR + k];
            const char* g = (const char*)(xt + (size_t)v * NC) + seg * 16;
            cp16(abase + SWZ((uint32_t)(r * 128 + seg * 16)), g);
        }
        cp_commit();
    };
    // W load for chunk k -> W stage (k & 1); one commit group.
    auto issue_W = [&](int k) {
        uint32_t wbase = sb + OFF_W + (k & 1) * W_STAGE;
        const char* wsrc = (const char*)(g_w + (size_t)k * NC * NC);
        #pragma unroll
        for (int j = 0; j < 2; j++) {
            int r = r0g + j * 32;   // 0..63
            uint32_t off = (uint32_t)(r * 128 + seg * 16);
            cp16(wbase + SWZ(off), wsrc + off);
        }
        cp_commit();
    };

    // ---- warp tiling: 4 M-warps x 2 N-warps; warp tile 32x32 ----
    const int wm = wid & 3;
    const int wn = wid >> 2;
    float acc[2][4][4];
    #pragma unroll
    for (int mt = 0; mt < 2; mt++)
        #pragma unroll
        for (int nt = 0; nt < 4; nt++)
            #pragma unroll
            for (int i = 0; i < 4; i++) acc[mt][nt][i] = 0.f;

    const uint32_t aRow = (uint32_t)(wm * 32 + (lid & 7) + 8 * ((lid >> 3) & 1)) << 7;
    const uint32_t aColLane = (uint32_t)(lid >> 4) << 4;
    const uint32_t bRow = (uint32_t)(wn * 32 + (lid & 7) + 8 * (lid >> 4)) << 7;
    const uint32_t bColLane = (uint32_t)((lid >> 3) & 1) << 4;

    // Asymmetric pipeline: A 3-stage/ahead-2, W 2-stage/ahead-1.
    // Per-thread commit FIFO at iter-k wait: ..., GW(k), GA(k+1), GW(k+1), GA(k+2)
    // wait_group 3 retires GW(k) and all older (incl. GA(k)); A keeps depth 2.
    // Stage safety (all warps pass trailing barrier of iter k-1 first):
    //   GA(k+2) writes A stage (k+2)%3 == (k-1)%3, consumed by MMA(k-1).
    //   GW(k+1) writes W stage (k+1)&1 == (k-1)&1, consumed by MMA(k-1).
    issue_A(0, 0);       // GA0
    issue_W(0);          // GW0
    issue_A(1, 1);       // GA1

    int astage = 0;      // k % 3, tracked incrementally
    for (int k = 0; k < KR; k++) {
        if (k + 1 < KR) issue_W(k + 1); else cp_commit();   // GW(k+1)
        int a2 = astage + 2; if (a2 >= 3) a2 -= 3;
        if (k + 2 < KR) issue_A(k + 2, a2); else cp_commit(); // GA(k+2)
        cp_wait3();
        __syncthreads();

        const uint32_t aT = sb + OFF_A + astage * A_STAGE;
        const uint32_t bT = sb + OFF_W + (k & 1) * W_STAGE;

        // Register-diet schedule: Bf[8] persists per ks; Af[4] per mt only.
        #pragma unroll
        for (int ks = 0; ks < 4; ks++) {
            const uint32_t kb = (uint32_t)(ks * 32);
            uint32_t Bf[8];
            #pragma unroll
            for (int p = 0; p < 2; p++) {
                uint32_t off = bRow + ((uint32_t)p << 11) + kb + bColLane;
                ldsm_x4(Bf[p * 4 + 0], Bf[p * 4 + 1], Bf[p * 4 + 2], Bf[p * 4 + 3],
                        bT + SWZ(off));
            }
            #pragma unroll
            for (int mt = 0; mt < 2; mt++) {
                uint32_t Af[4];
                uint32_t off = aRow + ((uint32_t)mt << 11) + kb + aColLane;
                ldsm_x4(Af[0], Af[1], Af[2], Af[3], aT + SWZ(off));
                #pragma unroll
                for (int nt = 0; nt < 4; nt++)
                    mma_f16(acc[mt][nt], Af[0], Af[1], Af[2], Af[3],
                            Bf[nt * 2], Bf[nt * 2 + 1]);
            }
        }
        __syncthreads();   // stage consumed by all warps before reuse next iters

        astage += 1; if (astage == 3) astage = 0;
    }

    // ---- epilogue: stage via smem for coalesced [o][v] stores ----
    float* s_out = (float*)(smem + OFF_A);   // 32 KB = A stages 0-1
    #pragma unroll
    for (int mt = 0; mt < 2; mt++) {
        int r = wm * 32 + mt * 16 + (lid >> 2);
        #pragma unroll
        for (int nt = 0; nt < 4; nt++) {
            int o = wn * 32 + nt * 8 + (lid & 3) * 2;
            s_out[(o + 0) * 128 + r]     = acc[mt][nt][0];
            s_out[(o + 1) * 128 + r]     = acc[mt][nt][1];
            s_out[(o + 0) * 128 + r + 8] = acc[mt][nt][2];
            s_out[(o + 1) * 128 + r + 8] = acc[mt][nt][3];
        }
    }
    __syncthreads();

    const float* bs = (const float*)(smem + OFF_BIAS);
    float* ob = out + (size_t)b * NC * NV + vbase;
    #pragma unroll
    for (int i = 0; i < 32; i++) {
        int idx = tid + i * 256;
        int o = idx >> 7, v = idx & 127;
        if (v < rows) ob[(size_t)o * NV + v] = s_out[idx] + bs[o];
    }
}

// ------------------------------ launch --------------------------------------
extern "C" void kernel_launch(void* const* d_in, const int* in_sizes, int n_in,
                              void* d_out, int out_size) {
    const float* x     = (const float*)d_in[0];
    const int*   neigh = (const int*)d_in[1];
    const float* W     = (const float*)d_in[2];
    const float* bias  = (const float*)d_in[3];
    float* out = (float*)d_out;

    cudaFuncSetAttribute(conv_main, cudaFuncAttributeMaxDynamicSharedMemorySize, SMEM_TOTAL);

    prep_w_kernel<<<(NC * KR * NC + 255) / 256, 256>>>(W);
    prep_x_kernel<<<dim3((NV + 63) / 64, NBATCH), 256>>>(x);
    conv_main<<<NTILES, 256, SMEM_TOTAL>>>(neigh, bias, out);
}

// round 13
// speedup vs baseline: 1.2058x; 1.0514x over previous
#include <cuda_runtime.h>
#include <cuda_fp16.h>
#include <cstdint>

#define NV 40962
#define KR 19
#define NC 64            // C_in == C_out == 64
#define NBATCH 4
#define TILE_M 128
#define TILES_PER_B 321  // ceil(40962/128)
#define NTILES (NBATCH * TILES_PER_B)

// prep_all grid split
#define XBLOCKS_PER_B 641                 // ceil(40962/64)
#define XBLOCKS (NBATCH * XBLOCKS_PER_B)  // 2564
#define WBLOCKS 304                       // ceil(64*19*64/256)
#define PREP_BLOCKS (XBLOCKS + WBLOCKS)

// -------- device scratch (allocation-free rule: __device__ globals) --------
// x[b][v][64] fp16, 128B per vertex row
__device__ __align__(1024) __half g_xt[(size_t)NBATCH * NV * NC];   // ~21 MB
// per-chunk W tile: g_w[k][o][64] fp16 (row = 128B)
__device__ __align__(1024) __half g_w[KR * NC * NC];                // 152 KB

// ---------------------------- helpers ----------------------------------
__device__ __forceinline__ uint32_t smem_to_u32(const void* p) {
    uint32_t a;
    asm("{ .reg .u64 t; cvta.to.shared.u64 t, %1; cvt.u32.u64 %0, t; }"
        : "=r"(a) : "l"(p));
    return a;
}

#define SWZ(off) ((off) ^ (((off) >> 3) & 0x70))

__device__ __forceinline__ void cp16(uint32_t saddr, const void* gaddr) {
    asm volatile("cp.async.cg.shared.global [%0], [%1], 16;"
                 :: "r"(saddr), "l"(gaddr) : "memory");
}
__device__ __forceinline__ void cp_commit() {
    asm volatile("cp.async.commit_group;" ::: "memory");
}
__device__ __forceinline__ void cp_wait1() {
    asm volatile("cp.async.wait_group 1;" ::: "memory");
}

__device__ __forceinline__ void ldsm_x4(uint32_t& r0, uint32_t& r1, uint32_t& r2,
                                        uint32_t& r3, uint32_t a) {
    asm volatile("ldmatrix.sync.aligned.m8n8.x4.shared.b16 {%0,%1,%2,%3}, [%4];"
                 : "=r"(r0), "=r"(r1), "=r"(r2), "=r"(r3) : "r"(a));
}

__device__ __forceinline__ void mma_f16(float* c, uint32_t a0, uint32_t a1,
                                        uint32_t a2, uint32_t a3,
                                        uint32_t b0, uint32_t b1) {
    asm volatile(
        "mma.sync.aligned.m16n8k16.row.col.f32.f16.f16.f32 "
        "{%0,%1,%2,%3}, {%4,%5,%6,%7}, {%8,%9}, {%0,%1,%2,%3};"
        : "+f"(c[0]), "+f"(c[1]), "+f"(c[2]), "+f"(c[3])
        : "r"(a0), "r"(a1), "r"(a2), "r"(a3), "r"(b0), "r"(b1));
}

// ------------------------------ fused prep kernel ----------------------------
// blocks [0, XBLOCKS): transpose x[b][c][v] -> g_xt[b][v][c] fp16
// blocks [XBLOCKS, PREP_BLOCKS): W[o][19*64] -> g_w[k][o][c] fp16
__global__ void prep_all(const float* __restrict__ x, const float* __restrict__ W) {
    __shared__ float s[64][65];
    int tid = threadIdx.x;  // 256
    if (blockIdx.x < XBLOCKS) {
        int b = blockIdx.x / XBLOCKS_PER_B;
        int v0 = (blockIdx.x % XBLOCKS_PER_B) * 64;
        for (int i = tid; i < 64 * 64; i += 256) {
            int c = i >> 6, vi = i & 63;
            int v = v0 + vi;
            s[c][vi] = (v < NV) ? x[((size_t)b * NC + c) * NV + v] : 0.f;
        }
        __syncthreads();
        for (int i = tid; i < 64 * 32; i += 256) {
            int vi = i >> 5, g = i & 31;
            int v = v0 + vi;
            if (v >= NV) continue;
            int c0 = g * 2;
            __half2 h2 = __floats2half2_rn(s[c0][vi], s[c0 + 1][vi]);
            *(__half2*)(g_xt + ((size_t)b * NV + v) * NC + c0) = h2;
        }
    } else {
        int i = (blockIdx.x - XBLOCKS) * 256 + tid;
        if (i < NC * KR * NC) {
            int o = i / (KR * NC);
            int kk = i % (KR * NC);
            int k = kk >> 6, c = kk & 63;
            g_w[((size_t)k * NC + o) * NC + c] = __float2half(W[i]);
        }
    }
}

// ------------------------------ main kernel ---------------------------------
// smem layout (bytes):
#define OFF_BIAS  0          // 64 floats, pad to 512
#define OFF_IDX   512        // 128*19*2 (u16) = 4864 -> ends 5376
#define OFF_A     6144       // 2 stages x (128 rows x 128B) = 32768 (1024-aligned)
#define OFF_W     38912      // 2 stages x (64 rows x 128B)  = 16384
#define SMEM_TOTAL 55296
#define A_STAGE 16384
#define W_STAGE 8192

__global__ __launch_bounds__(256, 3) void conv_main(const int* __restrict__ neigh,
                                                    const float* __restrict__ bias,
                                                    float* __restrict__ out) {
    extern __shared__ char smem[];
    uint32_t sb = smem_to_u32(smem);
    const int tid = threadIdx.x;
    const int wid = tid >> 5, lid = tid & 31;
    const int b = blockIdx.x / TILES_PER_B;
    const int t = blockIdx.x % TILES_PER_B;
    const int vbase = t * TILE_M;
    int rows = NV - vbase; if (rows > TILE_M) rows = TILE_M;

    if (tid < NC) ((float*)(smem + OFF_BIAS))[tid] = bias[tid];

    // neighbor indices -> smem as u16 (NV < 65536)
    unsigned short* s_idx = (unsigned short*)(smem + OFF_IDX);
    {
        int tot = rows * KR;
        const int* src = neigh + (size_t)vbase * KR;
        for (int i = tid; i < tot; i += 256) s_idx[i] = (unsigned short)src[i];
    }
    __syncthreads();

    const __half* xt = g_xt + (size_t)b * NV * NC;

    // ---- gather one chunk into stage (k & 1) ----
    const int seg = tid & 7;          // 16B segment in a 128B row
    const int r0g = tid >> 3;         // 0..31
    auto issue_chunk = [&](int k) {
        int stage = k & 1;
        uint32_t abase = sb + OFF_A + stage * A_STAGE;
        #pragma unroll
        for (int j = 0; j < 4; j++) {
            int r = r0g + j * 32;
            int rr = (r < rows) ? r : 0;
            uint32_t v = s_idx[rr * KR + k];
            const char* g = (const char*)(xt + (size_t)v * NC) + seg * 16;
            cp16(abase + SWZ((uint32_t)(r * 128 + seg * 16)), g);
        }
        uint32_t wbase = sb + OFF_W + stage * W_STAGE;
        const char* wsrc = (const char*)(g_w + (size_t)k * NC * NC);
        #pragma unroll
        for (int j = 0; j < 2; j++) {
            int r = r0g + j * 32;   // 0..63
            uint32_t off = (uint32_t)(r * 128 + seg * 16);
            cp16(wbase + SWZ(off), wsrc + off);
        }
        cp_commit();
    };

    // ---- warp tiling: 4 M-warps x 2 N-warps; warp tile 32x32 ----
    const int wm = wid & 3;
    const int wn = wid >> 2;
    float acc[2][4][4];
    #pragma unroll
    for (int mt = 0; mt < 2; mt++)
        #pragma unroll
        for (int nt = 0; nt < 4; nt++)
            #pragma unroll
            for (int i = 0; i < 4; i++) acc[mt][nt][i] = 0.f;

    // ldmatrix lane address components (tile-relative byte offsets, pre-swizzle)
    const uint32_t aRow = (uint32_t)(wm * 32 + (lid & 7) + 8 * ((lid >> 3) & 1)) << 7;
    const uint32_t aColLane = (uint32_t)(lid >> 4) << 4;
    const uint32_t bRow = (uint32_t)(wn * 32 + (lid & 7) + 8 * (lid >> 4)) << 7;
    const uint32_t bColLane = (uint32_t)((lid >> 3) & 1) << 4;

    // 2-stage ring, issue-ahead-1, two barriers per chunk (best-measured schedule):
    //   issue(k+1) writes stage (k+1)&1 == (k-1)&1, fully consumed by MMA(k-1)
    //   before the trailing barrier of iter k-1.
    //   wait_group 1 leaves only group k+1 pending => group k complete; the
    //   leading barrier publishes all threads' stage-k data before ldmatrix.
    issue_chunk(0);

    for (int k = 0; k < KR; k++) {
        if (k + 1 < KR) issue_chunk(k + 1);
        else cp_commit();            // keep per-thread group counts uniform
        cp_wait1();
        __syncthreads();

        const int stage = k & 1;
        const uint32_t aT = sb + OFF_A + stage * A_STAGE;
        const uint32_t bT = sb + OFF_W + stage * W_STAGE;

        // Register-diet schedule: Bf[8] persists per ks; Af[4] per mt only.
        #pragma unroll
        for (int ks = 0; ks < 4; ks++) {
            const uint32_t kb = (uint32_t)(ks * 32);
            uint32_t Bf[8];
            #pragma unroll
            for (int p = 0; p < 2; p++) {
                uint32_t off = bRow + ((uint32_t)p << 11) + kb + bColLane;
                ldsm_x4(Bf[p * 4 + 0], Bf[p * 4 + 1], Bf[p * 4 + 2], Bf[p * 4 + 3],
                        bT + SWZ(off));
            }
            #pragma unroll
            for (int mt = 0; mt < 2; mt++) {
                uint32_t Af[4];
                uint32_t off = aRow + ((uint32_t)mt << 11) + kb + aColLane;
                ldsm_x4(Af[0], Af[1], Af[2], Af[3], aT + SWZ(off));
                #pragma unroll
                for (int nt = 0; nt < 4; nt++)
                    mma_f16(acc[mt][nt], Af[0], Af[1], Af[2], Af[3],
                            Bf[nt * 2], Bf[nt * 2 + 1]);
            }
        }
        __syncthreads();   // stage consumed by all warps before issue(k+2)
    }

    // ---- epilogue: stage via smem for coalesced [o][v] stores ----
    float* s_out = (float*)(smem + OFF_A);   // 32 KB = both A stages
    #pragma unroll
    for (int mt = 0; mt < 2; mt++) {
        int r = wm * 32 + mt * 16 + (lid >> 2);
        #pragma unroll
        for (int nt = 0; nt < 4; nt++) {
            int o = wn * 32 + nt * 8 + (lid & 3) * 2;
            s_out[(o + 0) * 128 + r]     = acc[mt][nt][0];
            s_out[(o + 1) * 128 + r]     = acc[mt][nt][1];
            s_out[(o + 0) * 128 + r + 8] = acc[mt][nt][2];
            s_out[(o + 1) * 128 + r + 8] = acc[mt][nt][3];
        }
    }
    __syncthreads();

    const float* bs = (const float*)(smem + OFF_BIAS);
    float* ob = out + (size_t)b * NC * NV + vbase;
    #pragma unroll
    for (int i = 0; i < 32; i++) {
        int idx = tid + i * 256;
        int o = idx >> 7, v = idx & 127;
        if (v < rows) ob[(size_t)o * NV + v] = s_out[idx] + bs[o];
    }
}

// ------------------------------ launch --------------------------------------
extern "C" void kernel_launch(void* const* d_in, const int* in_sizes, int n_in,
                              void* d_out, int out_size) {
    const float* x     = (const float*)d_in[0];
    const int*   neigh = (const int*)d_in[1];
    const float* W     = (const float*)d_in[2];
    const float* bias  = (const float*)d_in[3];
    float* out = (float*)d_out;

    cudaFuncSetAttribute(conv_main, cudaFuncAttributeMaxDynamicSharedMemorySize, SMEM_TOTAL);

    prep_all<<<PREP_BLOCKS, 256>>>(x, W);
    conv_main<<<NTILES, 256, SMEM_TOTAL>>>(neigh, bias, out);
}